// round 14
// baseline (speedup 1.0000x reference)
#include <cuda_runtime.h>
#include <math.h>

#define BB 16
#define TT 512
#define NCH 32
#define DD 512
#define KQ 96          // 3*32 contraction length

#define BM 128
#define BN 32
#define XS2 260        // duplicated Xs row stride in floats (130 value-pairs)
#define BS2 36         // Bs row stride in floats (16B-aligned rows: 36*4=144)

typedef unsigned long long u64;

__device__ float g_T[TT * DD];     // sinusoid table: row r, col d
__device__ int   g_flag[BB * NCH]; // per-(b,n): 1 if rfft argmax == Nyquist bin

// packed fp32x2 FMA (SASS FFMA2): two independent full-precision fp32 FMAs
__device__ __forceinline__ u64 ffma2(u64 a, u64 b, u64 c) {
    u64 d;
    asm("fma.rn.f32x2 %0, %1, %2, %3;" : "=l"(d) : "l"(a), "l"(b), "l"(c));
    return d;
}
__device__ __forceinline__ float lo32(u64 v) { return __uint_as_float((unsigned)v); }
__device__ __forceinline__ float hi32(u64 v) { return __uint_as_float((unsigned)(v >> 32)); }

// ---------------------------------------------------------------------------
// Kernel 1: per-(b,n) DFT argmax over 257 rfft bins + build one table row.
// (unchanged from R11 — ~8us; fused kernel is this round's target)
// ---------------------------------------------------------------------------
__global__ __launch_bounds__(256) void dft_argmax_kernel(const float* __restrict__ x) {
    __shared__ float seq[TT];
    __shared__ float smax[256];
    __shared__ int   sidx[256];

    int bn = blockIdx.x;          // 0..511
    int b = bn >> 5;
    int n = bn & 31;
    int tid = threadIdx.x;

    {   // build sinusoid table row `bn`
        const float kconst = 0.01798894603f;       // log(10000)/512
        float div = expf(-(float)(2 * tid) * kconst);
        float ang = (float)bn * div;
        float s, c;
        sincosf(ang, &s, &c);
        ((float2*)g_T)[bn * (DD / 2) + tid] = make_float2(s, c);
    }

    seq[tid]       = x[(b * TT + tid) * NCH + n];
    seq[tid + 256] = x[(b * TT + tid + 256) * NCH + n];
    __syncthreads();

    float best;
    int   bidx;

    if (tid == 0) {
        float s0 = 0.f, s1 = 0.f;
        for (int t = 0; t < TT; t += 2) {
            float a = seq[t], c = seq[t + 1];
            s0 += a + c;
            s1 += a - c;
        }
        best = s0 * s0;
        bidx = 0;
        float m256 = s1 * s1;
        if (m256 > best) { best = m256; bidx = 256; }
    } else {
        int kk = tid;             // bins 1..255
        float th = 6.283185307179586f * (float)kk * (1.0f / 512.0f);
        float c4, s4;
        sincosf(4.0f * th, &s4, &c4);
        float c = 1.f, s = 0.f;
        float re[4] = {0.f, 0.f, 0.f, 0.f};
        float im[4] = {0.f, 0.f, 0.f, 0.f};

        for (int t = 0; t < TT; t += 4) {
            float v0 = seq[t], v1 = seq[t + 1], v2 = seq[t + 2], v3 = seq[t + 3];
            re[0] = fmaf(v0, c, re[0]);  im[0] = fmaf(v0, s, im[0]);
            re[1] = fmaf(v1, c, re[1]);  im[1] = fmaf(v1, s, im[1]);
            re[2] = fmaf(v2, c, re[2]);  im[2] = fmaf(v2, s, im[2]);
            re[3] = fmaf(v3, c, re[3]);  im[3] = fmaf(v3, s, im[3]);
            float cn = fmaf(c, c4, -s * s4);
            s = fmaf(s, c4, c * s4);
            c = cn;
        }
        float R = re[0], I = im[0];
#pragma unroll
        for (int j = 1; j < 4; j++) {
            float cj, sj;
            sincosf((float)j * th, &sj, &cj);
            R += re[j] * cj - im[j] * sj;
            I += im[j] * cj + re[j] * sj;
        }
        best = R * R + I * I;
        bidx = kk;
    }

    smax[tid] = best;
    sidx[tid] = bidx;
    __syncthreads();
    for (int sft = 128; sft > 0; sft >>= 1) {
        if (tid < sft) {
            bool take = (smax[tid + sft] > smax[tid]) ||
                        (smax[tid + sft] == smax[tid] && sidx[tid + sft] < sidx[tid]);
            if (take) { smax[tid] = smax[tid + sft]; sidx[tid] = sidx[tid + sft]; }
        }
        __syncthreads();
    }
    if (tid == 0) g_flag[bn] = (sidx[0] == 256) ? 1 : 0;
}

// ---------------------------------------------------------------------------
// Kernel 2: fused circular conv + temporal + cycle, FFMA2 edition.
// Tile 128(t) x 32(d), 256 threads, 4x4 microtile.
// Xs2 stores each input value DUPLICATED so (a,a) packs are a single LDS.64;
// Bs float4 rows give (b0,b1),(b2,b3) pairs for free. Inner loop per channel:
// 6 LDS.64 + 3 LDS.128 + 24 FFMA2 for 48 FMAs (0.71 instr/FMA vs 1.06).
// smem = 33.3K (Xs2) + 13.8K (Bs) + 0.9K (Trow) = 48.0KB -> 4 blocks/SM.
// ---------------------------------------------------------------------------
__global__ __launch_bounds__(256) void fused_main_kernel(
    const float* __restrict__ x,
    const int*   __restrict__ xm,
    const float* __restrict__ w,
    float*       __restrict__ out)
{
    __shared__ float Xs2[NCH * XS2];   // [c][2r], r = 0..129 (rows t0-1 .. t0+128), dup pairs
    __shared__ float Bs[KQ * BS2];     // [q][dd] = w[(d0+dd)*96 + q]
    __shared__ float Trow[7 * BN];     // table rows 0..6 at cols d0..d0+31
    __shared__ int   sCnt;

    int b  = blockIdx.z;
    int t0 = blockIdx.y * BM;
    int d0 = blockIdx.x * BN;
    int tid = threadIdx.x;

    // Xs2 load: coalesced gmem, duplicated float2 smem write
    for (int i = tid; i < (BM + 2) * NCH; i += 256) {
        int r = i >> 5;
        int c = i & 31;
        int tt = (t0 + r - 1) & (TT - 1);       // circular pad
        float v = x[(b * TT + tt) * NCH + c];
        ((float2*)&Xs2[c * XS2])[r] = make_float2(v, v);
    }
    // Bs load
    for (int i = tid; i < KQ * BN; i += 256) {
        int dd = i / KQ;
        int q  = i - dd * KQ;
        Bs[q * BS2 + dd] = w[(d0 + dd) * KQ + q];
    }
    // temporal rows 0..6 (7*32 = 224 <= 256 threads)
    if (tid < 7 * BN) {
        int r = tid >> 5;
        int c = tid & 31;
        Trow[r * BN + c] = g_T[r * DD + d0 + c];
    }
    // per-batch Nyquist count from flags
    if (tid < 32) {
        int f = g_flag[b * NCH + tid];
        int c = __reduce_add_sync(0xffffffffu, f);
        if (tid == 0) sCnt = c;
    }
    __syncthreads();

    int tx = tid & 7;        // d block: dl = tx*4 + j
    int ty = tid >> 3;       // t block: tl = ty*4 + i (ty 0..31)
    int tbase = ty * 4;

    u64 acc2[4][2];
#pragma unroll
    for (int i = 0; i < 4; i++) { acc2[i][0] = 0ull; acc2[i][1] = 0ull; }

#pragma unroll 2
    for (int c = 0; c < NCH; c++) {
        // 6 (a,a) pairs covering rows tbase .. tbase+5 (window 4 outputs + 2 taps)
        const u64* ap = (const u64*)&Xs2[c * XS2 + 2 * tbase];
        u64 aa[6];
#pragma unroll
        for (int j = 0; j < 6; j++) aa[j] = ap[j];
#pragma unroll
        for (int k = 0; k < 3; k++) {
            ulonglong2 bp = *(const ulonglong2*)&Bs[(c * 3 + k) * BS2 + tx * 4];
#pragma unroll
            for (int i = 0; i < 4; i++) {
                acc2[i][0] = ffma2(aa[i + k], bp.x, acc2[i][0]);
                acc2[i][1] = ffma2(aa[i + k], bp.y, acc2[i][1]);
            }
        }
    }

    int cnt = sCnt;
    float ca = (float)(32 - cnt) * 0.03125f;   // weight on T[t]
    float cc = (float)cnt * 0.03125f;          // weight on T[0] = (0,1,0,1,...)

#pragma unroll
    for (int i = 0; i < 4; i++) {
        int tg = t0 + tbase + i;
        int4 m = ((const int4*)xm)[b * TT + tg];
        float4 tm0 = *(const float4*)&Trow[m.x * BN + tx * 4];
        float4 tm1 = *(const float4*)&Trow[m.y * BN + tx * 4];
        float4 tm2 = *(const float4*)&Trow[m.z * BN + tx * 4];
        float4 tm3 = *(const float4*)&Trow[m.w * BN + tx * 4];
        float4 tt4 = *(const float4*)&g_T[tg * DD + d0 + tx * 4];
        float4 o;
        o.x = lo32(acc2[i][0]) + tm0.x + tm1.x + tm2.x + tm3.x + ca * tt4.x;
        o.y = hi32(acc2[i][0]) + tm0.y + tm1.y + tm2.y + tm3.y + ca * tt4.y + cc;
        o.z = lo32(acc2[i][1]) + tm0.z + tm1.z + tm2.z + tm3.z + ca * tt4.z;
        o.w = hi32(acc2[i][1]) + tm0.w + tm1.w + tm2.w + tm3.w + ca * tt4.w + cc;
        *(float4*)&out[((size_t)(b * TT + tg)) * DD + d0 + tx * 4] = o;
    }
}

// ---------------------------------------------------------------------------
extern "C" void kernel_launch(void* const* d_in, const int* in_sizes, int n_in,
                              void* d_out, int out_size) {
    const float* x  = (const float*)d_in[0];   // (16,512,32)
    const int*   xm = (const int*)  d_in[1];   // (16,512,4)
    const float* w  = (const float*)d_in[2];   // (512,32,3)
    float* out = (float*)d_out;                // (16,512,512)

    dft_argmax_kernel<<<BB * NCH, 256>>>(x);
    dim3 grid(DD / BN, TT / BM, BB);
    fused_main_kernel<<<grid, 256>>>(x, xm, w, out);
}

// round 15
// speedup vs baseline: 1.1157x; 1.1157x over previous
#include <cuda_runtime.h>
#include <math.h>

#define BB 16
#define TT 512
#define NCH 32
#define DD 512
#define KQ 96          // 3*32 contraction length

#define BM 128
#define BN 64
#define RS 132         // Xs row stride (floats), 16B-aligned windows
#define BS2 72         // Bs row stride (floats), 16B-aligned

typedef unsigned long long u64;

__device__ float g_T[TT * DD];     // sinusoid table: row r, col d
__device__ int   g_flag[BB * NCH]; // per-(b,n): 1 if rfft argmax == Nyquist bin

// packed fp32x2 FMA (SASS FFMA2): two independent full-precision fp32 FMAs
__device__ __forceinline__ u64 ffma2(u64 a, u64 b, u64 c) {
    u64 d;
    asm("fma.rn.f32x2 %0, %1, %2, %3;" : "=l"(d) : "l"(a), "l"(b), "l"(c));
    return d;
}
__device__ __forceinline__ u64 dup2(float a) {
    u64 d;
    asm("mov.b64 %0, {%1, %1};" : "=l"(d) : "f"(a));
    return d;
}
__device__ __forceinline__ float lo32(u64 v) { return __uint_as_float((unsigned)v); }
__device__ __forceinline__ float hi32(u64 v) { return __uint_as_float((unsigned)(v >> 32)); }

// ---------------------------------------------------------------------------
// Kernel 1: per-(b,n) DFT argmax over 257 rfft bins + build one table row.
// (unchanged — fused kernel is this round's single variable)
// ---------------------------------------------------------------------------
__global__ __launch_bounds__(256) void dft_argmax_kernel(const float* __restrict__ x) {
    __shared__ float seq[TT];
    __shared__ float smax[256];
    __shared__ int   sidx[256];

    int bn = blockIdx.x;          // 0..511
    int b = bn >> 5;
    int n = bn & 31;
    int tid = threadIdx.x;

    {   // build sinusoid table row `bn`
        const float kconst = 0.01798894603f;       // log(10000)/512
        float div = expf(-(float)(2 * tid) * kconst);
        float ang = (float)bn * div;
        float s, c;
        sincosf(ang, &s, &c);
        ((float2*)g_T)[bn * (DD / 2) + tid] = make_float2(s, c);
    }

    seq[tid]       = x[(b * TT + tid) * NCH + n];
    seq[tid + 256] = x[(b * TT + tid + 256) * NCH + n];
    __syncthreads();

    float best;
    int   bidx;

    if (tid == 0) {
        float s0 = 0.f, s1 = 0.f;
        for (int t = 0; t < TT; t += 2) {
            float a = seq[t], c = seq[t + 1];
            s0 += a + c;
            s1 += a - c;
        }
        best = s0 * s0;
        bidx = 0;
        float m256 = s1 * s1;
        if (m256 > best) { best = m256; bidx = 256; }
    } else {
        int kk = tid;             // bins 1..255
        float th = 6.283185307179586f * (float)kk * (1.0f / 512.0f);
        float c4, s4;
        sincosf(4.0f * th, &s4, &c4);
        float c = 1.f, s = 0.f;
        float re[4] = {0.f, 0.f, 0.f, 0.f};
        float im[4] = {0.f, 0.f, 0.f, 0.f};

        for (int t = 0; t < TT; t += 4) {
            float v0 = seq[t], v1 = seq[t + 1], v2 = seq[t + 2], v3 = seq[t + 3];
            re[0] = fmaf(v0, c, re[0]);  im[0] = fmaf(v0, s, im[0]);
            re[1] = fmaf(v1, c, re[1]);  im[1] = fmaf(v1, s, im[1]);
            re[2] = fmaf(v2, c, re[2]);  im[2] = fmaf(v2, s, im[2]);
            re[3] = fmaf(v3, c, re[3]);  im[3] = fmaf(v3, s, im[3]);
            float cn = fmaf(c, c4, -s * s4);
            s = fmaf(s, c4, c * s4);
            c = cn;
        }
        float R = re[0], I = im[0];
#pragma unroll
        for (int j = 1; j < 4; j++) {
            float cj, sj;
            sincosf((float)j * th, &sj, &cj);
            R += re[j] * cj - im[j] * sj;
            I += im[j] * cj + re[j] * sj;
        }
        best = R * R + I * I;
        bidx = kk;
    }

    smax[tid] = best;
    sidx[tid] = bidx;
    __syncthreads();
    for (int sft = 128; sft > 0; sft >>= 1) {
        if (tid < sft) {
            bool take = (smax[tid + sft] > smax[tid]) ||
                        (smax[tid + sft] == smax[tid] && sidx[tid + sft] < sidx[tid]);
            if (take) { smax[tid] = smax[tid + sft]; sidx[tid] = sidx[tid + sft]; }
        }
        __syncthreads();
    }
    if (tid == 0) g_flag[bn] = (sidx[0] == 256) ? 1 : 0;
}

// ---------------------------------------------------------------------------
// Kernel 2: fused circular conv + temporal + cycle — FFMA2 with R11 geometry.
// Tile 128(t) x 64(d), 256 threads, 8x4 microtile.
// A window (10 floats) from 3 LDS.128 of plain Xs, duplicated into (a,a)
// u64 packs in REGISTERS (10 mov.b64/channel). B LDS.128 gives native
// (b0,b1),(b2,b3) u64 pairs. Per channel: 6 LDS.128 + 10 packs + 48 FFMA2
// for 96 FMAs -> 0.67 instr/FMA (vs 1.06 scalar) at R11's LDS/FMA ratio.
// ---------------------------------------------------------------------------
__global__ __launch_bounds__(256) void fused_main_kernel(
    const float* __restrict__ x,
    const int*   __restrict__ xm,
    const float* __restrict__ w,
    float*       __restrict__ out)
{
    __shared__ float Xs[NCH * RS];     // [c][r], r = 0..129 (rows t0-1 .. t0+128)
    __shared__ float Bs[KQ * BS2];     // [q][dd] = w[(d0+dd)*96 + q]
    __shared__ float Trow[7 * BN];     // table rows 0..6 at cols d0..d0+63
    __shared__ int   sCnt;

    int b  = blockIdx.z;
    int t0 = blockIdx.y * BM;
    int d0 = blockIdx.x * BN;
    int tid = threadIdx.x;

    // Xs load: coalesced gmem, transposed smem write
    for (int i = tid; i < (BM + 2) * NCH; i += 256) {
        int r = i >> 5;
        int c = i & 31;
        int tt = (t0 + r - 1) & (TT - 1);       // circular pad
        Xs[c * RS + r] = x[(b * TT + tt) * NCH + c];
    }
    // Bs load: coalesced gmem (q fastest), strided smem write
    for (int i = tid; i < KQ * BN; i += 256) {
        int dd = i / KQ;
        int q  = i - dd * KQ;
        Bs[q * BS2 + dd] = w[(d0 + dd) * KQ + q];
    }
    // temporal rows 0..6 (448 elements -> loop)
    for (int i = tid; i < 7 * BN; i += 256) {
        int r = i / BN;
        int c = i - r * BN;
        Trow[r * BN + c] = g_T[r * DD + d0 + c];
    }
    // per-batch Nyquist count from flags
    if (tid < 32) {
        int f = g_flag[b * NCH + tid];
        int c = __reduce_add_sync(0xffffffffu, f);
        if (tid == 0) sCnt = c;
    }
    __syncthreads();

    int tx = tid & 15;       // d block: dl = tx*4 + j
    int ty = tid >> 4;       // t block: tl = ty*8 + i
    int tbase = ty * 8;

    u64 acc2[8][2];
#pragma unroll
    for (int i = 0; i < 8; i++) { acc2[i][0] = 0ull; acc2[i][1] = 0ull; }

#pragma unroll 2
    for (int c = 0; c < NCH; c++) {
        float4 a0 = *(const float4*)&Xs[c * RS + tbase];
        float4 a1 = *(const float4*)&Xs[c * RS + tbase + 4];
        float4 a2 = *(const float4*)&Xs[c * RS + tbase + 8];
        u64 ad[10];
        ad[0] = dup2(a0.x); ad[1] = dup2(a0.y); ad[2] = dup2(a0.z); ad[3] = dup2(a0.w);
        ad[4] = dup2(a1.x); ad[5] = dup2(a1.y); ad[6] = dup2(a1.z); ad[7] = dup2(a1.w);
        ad[8] = dup2(a2.x); ad[9] = dup2(a2.y);
#pragma unroll
        for (int k = 0; k < 3; k++) {
            ulonglong2 bp = *(const ulonglong2*)&Bs[(c * 3 + k) * BS2 + tx * 4];
#pragma unroll
            for (int i = 0; i < 8; i++) {
                acc2[i][0] = ffma2(ad[i + k], bp.x, acc2[i][0]);
                acc2[i][1] = ffma2(ad[i + k], bp.y, acc2[i][1]);
            }
        }
    }

    int cnt = sCnt;
    float ca = (float)(32 - cnt) * 0.03125f;   // weight on T[t]
    float cc = (float)cnt * 0.03125f;          // weight on T[0] = (0,1,0,1,...)

#pragma unroll
    for (int i = 0; i < 8; i++) {
        int tg = t0 + tbase + i;
        int4 m = ((const int4*)xm)[b * TT + tg];
        float4 tm0 = *(const float4*)&Trow[m.x * BN + tx * 4];
        float4 tm1 = *(const float4*)&Trow[m.y * BN + tx * 4];
        float4 tm2 = *(const float4*)&Trow[m.z * BN + tx * 4];
        float4 tm3 = *(const float4*)&Trow[m.w * BN + tx * 4];
        float4 tt4 = *(const float4*)&g_T[tg * DD + d0 + tx * 4];
        float4 o;
        o.x = lo32(acc2[i][0]) + tm0.x + tm1.x + tm2.x + tm3.x + ca * tt4.x;
        o.y = hi32(acc2[i][0]) + tm0.y + tm1.y + tm2.y + tm3.y + ca * tt4.y + cc;
        o.z = lo32(acc2[i][1]) + tm0.z + tm1.z + tm2.z + tm3.z + ca * tt4.z;
        o.w = hi32(acc2[i][1]) + tm0.w + tm1.w + tm2.w + tm3.w + ca * tt4.w + cc;
        *(float4*)&out[((size_t)(b * TT + tg)) * DD + d0 + tx * 4] = o;
    }
}

// ---------------------------------------------------------------------------
extern "C" void kernel_launch(void* const* d_in, const int* in_sizes, int n_in,
                              void* d_out, int out_size) {
    const float* x  = (const float*)d_in[0];   // (16,512,32)
    const int*   xm = (const int*)  d_in[1];   // (16,512,4)
    const float* w  = (const float*)d_in[2];   // (512,32,3)
    float* out = (float*)d_out;                // (16,512,512)

    dft_argmax_kernel<<<BB * NCH, 256>>>(x);
    dim3 grid(DD / BN, TT / BM, BB);
    fused_main_kernel<<<grid, 256>>>(x, xm, w, out);
}